// round 12
// baseline (speedup 1.0000x reference)
#include <cuda_runtime.h>

// ---------------------------------------------------------------------------
// OscillatorBank — XLA ReduceWindowRewriter(base_length=16) bit-replication
// (jax-CPU lowers cumsum via reduce_window; the rewriter recurses):
//
//   scan(128000): [8000,16] inner 16-seq prefix P1, row sums B1
//   scan(8000):   [500,16]  P2, sums B2
//   scan(500):    pad->512, [32,16] P3, sums B3
//   scan(32):     [2,16]    P4, sums B4
//   scan(2):      naive sequential
//   downward corrections, ONE f32 add each (offset 0 for first row => exact):
//     R4[i3] = fl(P4[i3] (+) O4excl[i3/16]),  O4excl = {0, B4[0]}
//     R3[i2] = fl(P3[i2] (+) R4[i2/16 - 1])
//     R2[i1] = fl(P2[i1] (+) R3[i1/16 - 1])
//     S[t]   = fl(P1[t]  (+) R2[t/16  - 1])
//   phase = exact fmodf(S, fl32(2*pi));  signal = sum_h (loud*amp)*sin(phase)
//
//   f0:[8,500,1] loudness:[8,500,1] harm_amps:[8,500,60] -> signal:[8,128000]
// ---------------------------------------------------------------------------

#define BB    8
#define TT    500
#define NH    60
#define LL    128000
#define SEQN  (BB * NH)     // 480 (b,h) sequences
#define B16   16
#define N1    8000          // LL/16
#define N2    500           // N1/16
#define N3    32            // 512/16 (500 padded to 512)

__device__ float g_B1[SEQN * N1];   // level-1 block sums (16 leaves each)
__device__ float g_R2[SEQN * N1];   // corrected level-2 scan values
__device__ float g_B2[SEQN * N2];   // level-2 block sums (16 B1 each)
__device__ float g_R3[SEQN * N2];   // corrected level-3 scan values

// Constants matching the reference's float32 values exactly.
__device__ __forceinline__ float RPOS() { return __fdiv_rn(499.0f, 127999.0f); }         // fl32(499)/fl32(127999)
__device__ __forceinline__ float CSC()  { return (float)(6.283185307179586 / 16000.0); } // fl32(2*pi/SR)
__device__ __forceinline__ float TPIF() { return (float)6.283185307179586; }             // fl32(2*pi)

__device__ __forceinline__ float interp1(float a, float b, float w) {
    // x0*(1-w) + x1*w, no FMA contraction (XLA emits plain fmul/fadd)
    return __fadd_rn(__fmul_rn(a, __fsub_rn(1.0f, w)), __fmul_rn(b, w));
}

// Bit-exact f32 phase-increment leaf v(l) for harmonic kf of batch-row f0b.
__device__ __forceinline__ float leafv(const float* __restrict__ f0b, int l, float kf, float rpos) {
    float pos = __fmul_rn((float)l, rpos);
    int i0 = (int)pos;                 // floor (pos >= 0)
    if (i0 > TT - 2) i0 = TT - 2;
    float w  = __fsub_rn(pos, (float)i0);
    float z0 = __fmul_rn(__fmul_rn(__ldg(f0b + i0),     kf), CSC());
    float z1 = __fmul_rn(__fmul_rn(__ldg(f0b + i0 + 1), kf), CSC());
    return interp1(z0, z1, w);
}

// Exact fmodf(x, fl32(2*pi)) for x >= 0 (bit-identical to jnp.mod for x>=0):
// x and q*Y are multiples of 2^-21, |true rem| < 8 -> exactly representable;
// the single-rounded FMA recovers it (one +-1 fixup on q).
__device__ __forceinline__ float exact_mod_2pi(float x) {
    const float y = TPIF();
    float q = truncf(__fmul_rn(x, 0.15915494f));   // ~1/2pi; q off by at most 1
    float r = __fmaf_rn(-q, y, x);
    if (r < 0.0f)     r = __fmaf_rn(-(q - 1.0f), y, x);
    else if (r >= y)  r = __fmaf_rn(-(q + 1.0f), y, x);
    return r;
}

// ---------------------------------------------------------------------------
// K1: level-1 block sums. One thread per (seq, 16-leaf block). 3.84M threads.
// ---------------------------------------------------------------------------
__global__ void k_b1(const float* __restrict__ f0) {
    int idx = blockIdx.x * blockDim.x + threadIdx.x;
    if (idx >= SEQN * N1) return;
    int seq = idx / N1, m = idx - seq * N1;
    int b = seq / NH, h = seq - b * NH;
    float kf = (float)(h + 1);
    float rpos = RPOS();
    const float* f0b = f0 + b * TT;
    float p = 0.0f;
    int l0 = m * B16;
    #pragma unroll
    for (int j = 0; j < B16; j++)
        p = __fadd_rn(p, leafv(f0b, l0 + j, kf, rpos));   // left-to-right
    g_B1[idx] = p;
}

// ---------------------------------------------------------------------------
// K2a: level-2 block sums. One thread per (seq, i2). 240k threads.
// ---------------------------------------------------------------------------
__global__ void k_b2() {
    int idx = blockIdx.x * blockDim.x + threadIdx.x;
    if (idx >= SEQN * N2) return;
    int seq = idx / N2, i2 = idx - seq * N2;
    const float* B1 = g_B1 + seq * N1 + i2 * B16;
    float p = 0.0f;
    #pragma unroll
    for (int j = 0; j < B16; j++) p = __fadd_rn(p, B1[j]);
    g_B2[idx] = p;
}

// ---------------------------------------------------------------------------
// K2b: levels 3..5 per sequence -> corrected R3[500]. One thread per seq.
// ---------------------------------------------------------------------------
__global__ void k_r3() {
    int seq = blockIdx.x * blockDim.x + threadIdx.x;
    if (seq >= SEQN) return;
    const float* B2 = g_B2 + seq * N2;
    float* R3 = g_R3 + seq * N2;

    // B3[32]: sums of 16 B2 entries (500 padded to 512 with zeros: fl(x+0)=x,
    // so we just stop at the real entries — bit-identical).
    float B3[N3];
    for (int i3 = 0; i3 < N3; i3++) {
        float p = 0.0f;
        for (int j = 0; j < B16; j++) {
            int k = i3 * B16 + j;
            if (k >= N2) break;
            p = __fadd_rn(p, B2[k]);
        }
        B3[i3] = p;
    }
    // B4[2] and naive scan(2) -> exclusive offsets {0, B4[0]}
    float B40 = 0.0f, B41 = 0.0f;
    for (int j = 0; j < B16; j++) B40 = __fadd_rn(B40, B3[j]);
    for (int j = 0; j < B16; j++) B41 = __fadd_rn(B41, B3[B16 + j]);
    (void)B41;
    // R4[32] = fl(P4 + O4excl)   (row 0 offset 0 -> exact)
    float R4[N3];
    {
        float p = 0.0f;
        for (int j = 0; j < B16; j++) { p = __fadd_rn(p, B3[j]);        R4[j]       = p; }
        p = 0.0f;
        for (int j = 0; j < B16; j++) { p = __fadd_rn(p, B3[B16 + j]); R4[B16 + j] = __fadd_rn(p, B40); }
    }
    // R3[500] = fl(P3 + R4[row-1])   (row 0 offset 0 -> exact)
    for (int r = 0; r < N3; r++) {
        float off = (r > 0) ? R4[r - 1] : 0.0f;
        float p = 0.0f;
        for (int j = 0; j < B16; j++) {
            int k = r * B16 + j;
            if (k >= N2) break;
            p = __fadd_rn(p, B2[k]);
            R3[k] = (r > 0) ? __fadd_rn(p, off) : p;   // fl(p+0)=p
        }
    }
}

// ---------------------------------------------------------------------------
// K2c: corrected level-2 values R2[8000]. One thread per (seq, row r<500).
// ---------------------------------------------------------------------------
__global__ void k_r2() {
    int idx = blockIdx.x * blockDim.x + threadIdx.x;
    if (idx >= SEQN * N2) return;
    int seq = idx / N2, r = idx - seq * N2;
    float off = (r > 0) ? g_R3[seq * N2 + r - 1] : 0.0f;
    const float* B1 = g_B1 + seq * N1 + r * B16;
    float* R2 = g_R2 + seq * N1 + r * B16;
    float p = 0.0f;
    #pragma unroll
    for (int j = 0; j < B16; j++) {
        p = __fadd_rn(p, B1[j]);
        R2[j] = (r > 0) ? __fadd_rn(p, off) : p;       // fl(p+0)=p
    }
}

// ---------------------------------------------------------------------------
// K3: fused final. grid (1000, 8) x 64. Each CTA handles 8 consecutive
// 16-blocks of t. Thread h runs the 16-step P1 chain for harmonic h,
// S = fl(P1 + R2[m-1]), exact mod, __sinf, amp/loud interp; 16 reducer
// threads sum the 60 harmonics per sample (sequential h order).
// ---------------------------------------------------------------------------
__global__ void __launch_bounds__(64) k_osc(const float* __restrict__ f0,
                                            const float* __restrict__ loud,
                                            const float* __restrict__ amps,
                                            float* __restrict__ out) {
    int b = blockIdx.y;
    int h = threadIdx.x;
    bool act = (h < NH);
    float kf = (float)(h + 1);
    float rpos = RPOS();

    const float* f0b = f0   + b * TT;
    const float* ldb = loud + b * TT;
    const float* Ab  = amps + (size_t)b * TT * NH;

    __shared__ float shp[NH * 17];

    #pragma unroll 1
    for (int s = 0; s < 8; s++) {
        int m = blockIdx.x * 8 + s;                    // [0, 8000)
        float off = 0.0f;
        if (act && m > 0) off = __ldg(&g_R2[(b * NH + h) * N1 + m - 1]);
        int l0 = m * B16;

        if (act) {
            float p = 0.0f;
            #pragma unroll
            for (int j = 0; j < B16; j++) {
                int l = l0 + j;
                float pos = __fmul_rn((float)l, rpos);
                int i0 = (int)pos;
                if (i0 > TT - 2) i0 = TT - 2;
                float w  = __fsub_rn(pos, (float)i0);
                float f00 = __ldg(f0b + i0), f01 = __ldg(f0b + i0 + 1);
                float z0 = __fmul_rn(__fmul_rn(f00, kf), CSC());
                float z1 = __fmul_rn(__fmul_rn(f01, kf), CSC());
                p = __fadd_rn(p, interp1(z0, z1, w));          // P1 chain
                // amp (masked per frame endpoint via pre-scale harmonics)
                float a0 = (__fmul_rn(f00, kf) > 8000.0f) ? 0.0f : __ldg(Ab + i0 * NH + h);
                float a1 = (__fmul_rn(f01, kf) > 8000.0f) ? 0.0f : __ldg(Ab + (i0 + 1) * NH + h);
                float av = interp1(a0, a1, w);
                float prod = 0.0f;
                if (av != 0.0f) {                              // skipped terms are +-0
                    float S  = (m > 0) ? __fadd_rn(p, off) : p; // single correction add
                    float sn = __sinf(exact_mod_2pi(S));
                    float lv = interp1(__ldg(ldb + i0), __ldg(ldb + i0 + 1), w);
                    prod = __fmul_rn(__fmul_rn(lv, av), sn);
                }
                shp[h * 17 + j] = prod;
            }
        }
        __syncthreads();
        if (h < B16) {
            float acc = 0.0f;
            #pragma unroll
            for (int hh = 0; hh < NH; hh++)
                acc = __fadd_rn(acc, shp[hh * 17 + h]);        // sequential h order
            out[(size_t)b * LL + l0 + h] = acc;
        }
        __syncthreads();
    }
}

// ---------------------------------------------------------------------------
extern "C" void kernel_launch(void* const* d_in, const int* in_sizes, int n_in,
                              void* d_out, int out_size) {
    const float* f0   = (const float*)d_in[0];   // [8,500,1]
    const float* loud = (const float*)d_in[1];   // [8,500,1]
    const float* amps = (const float*)d_in[2];   // [8,500,60]
    float* out = (float*)d_out;                  // [8,128000]
    (void)in_sizes; (void)n_in; (void)out_size;

    k_b1<<<(SEQN * N1 + 255) / 256, 256>>>(f0);
    k_b2<<<(SEQN * N2 + 127) / 128, 128>>>();
    k_r3<<<(SEQN + 63) / 64, 64>>>();
    k_r2<<<(SEQN * N2 + 127) / 128, 128>>>();
    dim3 g3(N1 / 8, BB);
    k_osc<<<g3, 64>>>(f0, loud, amps, out);
}

// round 13
// speedup vs baseline: 2.2930x; 2.2930x over previous
#include <cuda_runtime.h>

// ---------------------------------------------------------------------------
// OscillatorBank — XLA ReduceWindowRewriter(base_length=16) bit-replication.
// (Confirmed in R11: rel_err 2.96e-7.) This round: performance restructure,
// phase path bit-identical.
//
//   f0:[8,500,1] loudness:[8,500,1] harm_amps:[8,500,60] -> signal:[8,128000]
// ---------------------------------------------------------------------------

#define BB    8
#define TT    500
#define NH    60
#define LL    128000
#define SEQN  (BB * NH)     // 480 (b,h) sequences
#define B16   16
#define N1    8000          // LL/16
#define N2    500           // N1/16
#define N3    32

__device__ float g_z [BB * TT * NH];   // fl(fl(f0*k)*CSC), layout [b][frame][h]
__device__ float g_am[BB * TT * NH];   // masked amps,      layout [b][frame][h]
__device__ float g_B1[SEQN * N1];      // level-1 block sums
__device__ float g_R2[SEQN * N1];      // corrected level-2 scan values
__device__ float g_B2[SEQN * N2];      // level-2 block sums
__device__ float g_R3[SEQN * N2];      // corrected level-3 scan values

__device__ __forceinline__ float RPOS() { return __fdiv_rn(499.0f, 127999.0f); }
__device__ __forceinline__ float CSC()  { return (float)(6.283185307179586 / 16000.0); }
__device__ __forceinline__ float TPIF() { return (float)6.283185307179586; }

__device__ __forceinline__ float interp1(float a, float b, float w) {
    return __fadd_rn(__fmul_rn(a, __fsub_rn(1.0f, w)), __fmul_rn(b, w));
}

// Exact fmodf(x, fl32(2*pi)) for x >= 0 (bit-identical to jnp.mod for x>=0).
__device__ __forceinline__ float exact_mod_2pi(float x) {
    const float y = TPIF();
    float q = truncf(__fmul_rn(x, 0.15915494f));
    float r = __fmaf_rn(-q, y, x);
    if (r < 0.0f)     r = __fmaf_rn(-(q - 1.0f), y, x);
    else if (r >= y)  r = __fmaf_rn(-(q + 1.0f), y, x);
    return r;
}

// ---------------------------------------------------------------------------
// KZ: precompute z and masked-amp tables. 240k threads.
//   z  = fl(fl(f0*kf)*CSC)            (bit-identical to inline computation)
//   am = (fl(f0*kf) > 8000) ? 0 : amp (bit-identical mask semantics)
// ---------------------------------------------------------------------------
__global__ void k_z(const float* __restrict__ f0, const float* __restrict__ amps) {
    int idx = blockIdx.x * blockDim.x + threadIdx.x;   // (b*500+i)*60+h
    if (idx >= BB * TT * NH) return;
    int h  = idx % NH;
    int bi = idx / NH;                                  // b*500+i
    float f  = __ldg(f0 + bi);
    float kf = (float)(h + 1);
    float fk = __fmul_rn(f, kf);
    g_z[idx]  = __fmul_rn(fk, CSC());
    g_am[idx] = (fk > 8000.0f) ? 0.0f : __ldg(amps + idx);
}

// ---------------------------------------------------------------------------
// K1: level-1 block sums (16 leaves, strict left-to-right) + fused level-2
// sums via half-warp shuffles. Warp covers 2 rows (32 consecutive blocks).
// grid 15000 x 256 (8 warps/CTA; 480*250 warps total).
// ---------------------------------------------------------------------------
__global__ void __launch_bounds__(256) k_b1(void) {
    int gw   = blockIdx.x * 8 + (threadIdx.x >> 5);
    int lane = threadIdx.x & 31;
    int seq  = gw / 250;
    int pr   = gw - seq * 250;
    int row  = pr * 2 + (lane >> 4);                   // [0,500)
    int m    = row * B16 + (lane & 15);                // [0,8000)
    int b = seq / NH, h = seq - b * NH;
    float rpos = RPOS();

    const float* zb = g_z + (size_t)b * TT * NH + h;

    float p  = 0.0f;
    float lf = (float)(m * B16);
    #pragma unroll
    for (int j = 0; j < B16; j++) {
        float pos = __fmul_rn(lf, rpos);
        int i0 = (int)pos; if (i0 > TT - 2) i0 = TT - 2;
        float w  = __fsub_rn(pos, (float)i0);
        float z0 = __ldg(zb + i0 * NH);
        float z1 = __ldg(zb + (i0 + 1) * NH);
        p  = __fadd_rn(p, interp1(z0, z1, w));
        lf = __fadd_rn(lf, 1.0f);                      // exact (< 2^24)
    }
    g_B1[seq * N1 + m] = p;

    // B2[row] = sequential left-to-right sum of the 16 lane values
    int base = (lane & 16);                            // 0 or 16
    float s = 0.0f;
    #pragma unroll
    for (int j = 0; j < B16; j++)
        s = __fadd_rn(s, __shfl_sync(0xffffffffu, p, base + j));
    if ((lane & 15) == 0)
        g_B2[seq * N2 + row] = s;
}

// ---------------------------------------------------------------------------
// K2b: levels 3..5 -> corrected R3[500]. One warp per seq. grid 120 x 128.
// ---------------------------------------------------------------------------
__global__ void k_r3(void) {
    int warp = blockIdx.x * 4 + (threadIdx.x >> 5);
    if (warp >= SEQN) return;
    int seq  = warp;
    int lane = threadIdx.x & 31;                       // level-3 row r = lane
    const float* B2 = g_B2 + seq * N2;
    float* R3 = g_R3 + seq * N2;

    // B3[lane]: sequential sum of up to 16 B2 entries (row 31 has 4)
    float b3 = 0.0f;
    for (int j = 0; j < B16; j++) {
        int k = lane * B16 + j;
        if (k >= N2) break;
        b3 = __fadd_rn(b3, B2[k]);
    }
    // P4[lane]: sequential prefix of B3 within each half of 16
    int hb = lane & 16;
    float p4 = 0.0f;
    #pragma unroll
    for (int j = 0; j < B16; j++) {
        float t = __shfl_sync(0xffffffffu, b3, hb + j);
        if (j <= (lane & 15)) p4 = __fadd_rn(p4, t);
    }
    float b40 = __shfl_sync(0xffffffffu, p4, 15);      // sum of first half
    float r4  = (lane < 16) ? p4 : __fadd_rn(p4, b40); // row 0 offset 0 exact
    float off = __shfl_up_sync(0xffffffffu, r4, 1);    // R4[lane-1]

    // R3 row: p chain over B2, single correction add (row 0: value = p)
    float p = 0.0f;
    for (int j = 0; j < B16; j++) {
        int k = lane * B16 + j;
        if (k >= N2) break;
        p = __fadd_rn(p, B2[k]);
        R3[k] = (lane > 0) ? __fadd_rn(p, off) : p;
    }
}

// ---------------------------------------------------------------------------
// K2c: corrected level-2 values R2[8000]. CTA per seq, smem-staged (stride-17
// padding: coalesced global, conflict-free chains). grid 480 x 512.
// ---------------------------------------------------------------------------
__global__ void __launch_bounds__(512) k_r2(void) {
    int seq = blockIdx.x;
    int tid = threadIdx.x;
    __shared__ float sb[8500];                         // 8000 + row pads

    const float* B1 = g_B1 + seq * N1;
    for (int q = tid; q < N1; q += 512)
        sb[q + (q >> 4)] = B1[q];
    __syncthreads();

    if (tid < N2) {
        int r = tid;
        float off = (r > 0) ? __ldg(&g_R3[seq * N2 + r - 1]) : 0.0f;
        int sbase = r * 17;
        float p = 0.0f;
        #pragma unroll
        for (int j = 0; j < B16; j++) {
            p = __fadd_rn(p, sb[sbase + j]);
            sb[sbase + j] = (r > 0) ? __fadd_rn(p, off) : p;  // fl(p+0)=p
        }
    }
    __syncthreads();

    float* R2 = g_R2 + seq * N1;
    for (int q = tid; q < N1; q += 512)
        R2[q] = sb[q + (q >> 4)];
}

// ---------------------------------------------------------------------------
// K3: fused final. grid (2000, 8) x 256 = 4 slots x 64 threads.
// Thread h runs the 16-step P1 chain for its slot's block m,
// S = fl(P1 + R2[m-1]) (off = 0.0 for m==0, exact), exact mod, __sinf,
// amp interp; prod = av*sin staged in smem. 16 reducers per slot sum the
// 60 harmonics (sequential h order) and apply the h-invariant loudness.
// Blocks whose amp endpoints are all masked are skipped entirely (exact +-0).
// ---------------------------------------------------------------------------
__global__ void __launch_bounds__(256) k_osc(const float* __restrict__ loud,
                                             float* __restrict__ out) {
    int slot = threadIdx.x >> 6;                       // 0..3
    int h    = threadIdx.x & 63;
    int m    = blockIdx.x * 4 + slot;                  // [0, 8000)
    int b    = blockIdx.y;
    float rpos = RPOS();

    __shared__ float shp[4 * NH * 17];
    float* shrow = shp + (slot * NH + h) * 17;

    if (h < NH) {
        int seq = b * NH + h;
        int l0  = m * B16;

        // frame range of this block (spans at most 2 frames)
        float posf = __fmul_rn((float)l0, rpos);
        int i0f = (int)posf; if (i0f > TT - 2) i0f = TT - 2;
        float posl = __fmul_rn((float)(l0 + 15), rpos);
        int i0l = (int)posl; if (i0l > TT - 2) i0l = TT - 2;

        const float* amb = g_am + (size_t)b * TT * NH + h;
        float am0 = __ldg(amb + i0f * NH);
        float am1 = __ldg(amb + (i0f + 1) * NH);
        float am2 = __ldg(amb + (i0l + 1) * NH);

        if ((am0 == 0.0f) & (am1 == 0.0f) & (am2 == 0.0f)) {
            #pragma unroll
            for (int j = 0; j < B16; j++) shrow[j] = 0.0f;   // exact +-0 terms
        } else {
            float off = (m > 0) ? __ldg(&g_R2[seq * N1 + m - 1]) : 0.0f;
            const float* zb = g_z + (size_t)b * TT * NH + h;

            float p  = 0.0f;
            float lf = (float)l0;
            #pragma unroll
            for (int j = 0; j < B16; j++) {
                float pos = __fmul_rn(lf, rpos);
                int i0 = (int)pos; if (i0 > TT - 2) i0 = TT - 2;
                float w   = __fsub_rn(pos, (float)i0);
                float omw = __fsub_rn(1.0f, w);
                int zi = i0 * NH;
                float z0 = __ldg(zb + zi), z1 = __ldg(zb + zi + NH);
                p = __fadd_rn(p, __fadd_rn(__fmul_rn(z0, omw), __fmul_rn(z1, w)));
                float S  = __fadd_rn(p, off);                 // off=0 exact for m==0
                float sn = __sinf(exact_mod_2pi(S));
                float a0 = __ldg(amb + zi), a1 = __ldg(amb + zi + NH);
                float av = __fadd_rn(__fmul_rn(a0, omw), __fmul_rn(a1, w));
                shrow[j] = __fmul_rn(av, sn);
                lf = __fadd_rn(lf, 1.0f);
            }
        }
    }
    __syncthreads();

    if (h < B16) {
        int t = m * B16 + h;
        float pos = __fmul_rn((float)t, rpos);
        int i0 = (int)pos; if (i0 > TT - 2) i0 = TT - 2;
        float w  = __fsub_rn(pos, (float)i0);
        const float* ldb = loud + b * TT;
        float lv = interp1(__ldg(ldb + i0), __ldg(ldb + i0 + 1), w);

        const float* sl = shp + slot * NH * 17 + h;
        float acc = 0.0f;
        #pragma unroll
        for (int hh = 0; hh < NH; hh++)
            acc = __fadd_rn(acc, sl[hh * 17]);                // sequential h order
        out[(size_t)b * LL + t] = __fmul_rn(lv, acc);
    }
}

// ---------------------------------------------------------------------------
extern "C" void kernel_launch(void* const* d_in, const int* in_sizes, int n_in,
                              void* d_out, int out_size) {
    const float* f0   = (const float*)d_in[0];   // [8,500,1]
    const float* loud = (const float*)d_in[1];   // [8,500,1]
    const float* amps = (const float*)d_in[2];   // [8,500,60]
    float* out = (float*)d_out;                  // [8,128000]
    (void)in_sizes; (void)n_in; (void)out_size;

    k_z<<<(BB * TT * NH + 255) / 256, 256>>>(f0, amps);
    k_b1<<<15000, 256>>>();
    k_r3<<<(SEQN + 3) / 4, 128>>>();
    k_r2<<<SEQN, 512>>>();
    dim3 g3(N1 / 4, BB);
    k_osc<<<g3, 256>>>(loud, out);
}

// round 14
// speedup vs baseline: 2.4037x; 1.0483x over previous
#include <cuda_runtime.h>

// ---------------------------------------------------------------------------
// OscillatorBank — XLA ReduceWindowRewriter(base_length=16) bit-replication.
// (Scheme confirmed R11; perf rounds since.) Phase path bit-identical.
//   f0:[8,500,1] loudness:[8,500,1] harm_amps:[8,500,60] -> signal:[8,128000]
// ---------------------------------------------------------------------------

#define BB    8
#define TT    500
#define NH    60
#define LL    128000
#define SEQN  (BB * NH)     // 480 (b,h) sequences
#define B16   16
#define N1    8000          // LL/16
#define N2    500           // N1/16

__device__ float g_z  [BB * TT * NH];  // fl(fl(f0*k)*CSC), layout [b][frame][h]
__device__ float g_am [BB * TT * NH];  // masked amps,      layout [b][frame][h]
__device__ float g_B1 [SEQN * N1];     // level-1 block sums
__device__ float g_B2 [SEQN * N2];     // level-2 block sums
__device__ float g_R2 [SEQN * N1];     // corrected level-2 values [seq][m]
__device__ float g_R2T[BB * N1 * NH];  // transposed: [b][m][h]

__device__ __forceinline__ float RPOS() { return __fdiv_rn(499.0f, 127999.0f); }
__device__ __forceinline__ float CSC()  { return (float)(6.283185307179586 / 16000.0); }
__device__ __forceinline__ float TPIF() { return (float)6.283185307179586; }

__device__ __forceinline__ float interp1(float a, float b, float w) {
    return __fadd_rn(__fmul_rn(a, __fsub_rn(1.0f, w)), __fmul_rn(b, w));
}

// Exact fmodf(x, fl32(2*pi)) for x >= 0 (bit-identical to jnp.mod for x>=0).
__device__ __forceinline__ float exact_mod_2pi(float x) {
    const float y = TPIF();
    float q = truncf(__fmul_rn(x, 0.15915494f));
    float r = __fmaf_rn(-q, y, x);
    if (r < 0.0f)     r = __fmaf_rn(-(q - 1.0f), y, x);
    else if (r >= y)  r = __fmaf_rn(-(q + 1.0f), y, x);
    return r;
}

// ---------------------------------------------------------------------------
// KZ: precompute z and masked-amp tables (bit-identical values). 240k threads.
// ---------------------------------------------------------------------------
__global__ void k_z(const float* __restrict__ f0, const float* __restrict__ amps) {
    int idx = blockIdx.x * blockDim.x + threadIdx.x;   // (b*500+i)*60+h
    if (idx >= BB * TT * NH) return;
    int h  = idx % NH;
    int bi = idx / NH;
    float f  = __ldg(f0 + bi);
    float kf = (float)(h + 1);
    float fk = __fmul_rn(f, kf);
    g_z[idx]  = __fmul_rn(fk, CSC());
    g_am[idx] = (fk > 8000.0f) ? 0.0f : __ldg(amps + idx);
}

// ---------------------------------------------------------------------------
// K1: level-1 block sums (16 leaves, strict left-to-right) + fused level-2
// sums via half-warp shuffles. A 16-block spans <=2 frames: z loads hoisted.
// grid 15000 x 256.
// ---------------------------------------------------------------------------
__global__ void __launch_bounds__(256) k_b1(void) {
    int gw   = blockIdx.x * 8 + (threadIdx.x >> 5);
    int lane = threadIdx.x & 31;
    int seq  = gw / 250;
    int pr   = gw - seq * 250;
    int row  = pr * 2 + (lane >> 4);                   // [0,500)
    int m    = row * B16 + (lane & 15);                // [0,8000)
    int b = seq / NH, h = seq - b * NH;
    float rpos = RPOS();
    const float* zb = g_z + (size_t)b * TT * NH + h;

    int l0 = m * B16;
    float posf = __fmul_rn((float)l0, rpos);
    int i0f = (int)posf; if (i0f > TT - 2) i0f = TT - 2;
    float posl = __fmul_rn((float)(l0 + 15), rpos);
    int i0l = (int)posl; if (i0l > TT - 2) i0l = TT - 2;
    float zf0 = __ldg(zb + i0f * NH), zf1 = __ldg(zb + (i0f + 1) * NH);
    float zl0 = __ldg(zb + i0l * NH), zl1 = __ldg(zb + (i0l + 1) * NH);
    float fi0f = (float)i0f, fi0l = (float)i0l;

    float p = 0.0f, lf = (float)l0;
    #pragma unroll
    for (int j = 0; j < B16; j++) {
        float pos = __fmul_rn(lf, rpos);
        int i0 = (int)pos; if (i0 > TT - 2) i0 = TT - 2;
        bool sec = (i0 > i0f);
        float fi0 = sec ? fi0l : fi0f;
        float z0  = sec ? zl0  : zf0;
        float z1  = sec ? zl1  : zf1;
        float w   = __fsub_rn(pos, fi0);
        float omw = __fsub_rn(1.0f, w);
        p  = __fadd_rn(p, __fadd_rn(__fmul_rn(z0, omw), __fmul_rn(z1, w)));
        lf = __fadd_rn(lf, 1.0f);                      // exact (< 2^24)
    }
    g_B1[seq * N1 + m] = p;

    // B2[row] = sequential left-to-right sum of the 16 lane values
    int base = (lane & 16);
    float s = 0.0f;
    #pragma unroll
    for (int j = 0; j < B16; j++)
        s = __fadd_rn(s, __shfl_sync(0xffffffffu, p, base + j));
    if ((lane & 15) == 0)
        g_B2[seq * N2 + row] = s;
}

// ---------------------------------------------------------------------------
// K2: fused levels 3..5 (warp 0 -> smem R3) + corrected level-2 R2[8000].
// CTA per seq, smem-staged with stride-17 padding. grid 480 x 512.
// ---------------------------------------------------------------------------
__global__ void __launch_bounds__(512) k_r2(void) {
    int seq = blockIdx.x;
    int tid = threadIdx.x;
    __shared__ float sb[8500];                         // 8000 + row pads
    __shared__ float sR3[N2];

    const float* B1 = g_B1 + seq * N1;
    for (int q = tid; q < N1; q += 512)
        sb[q + (q >> 4)] = B1[q];

    if (tid < 32) {                                    // warp 0: R3[500]
        int lane = tid;
        const float* B2 = g_B2 + seq * N2;
        float b3 = 0.0f;                               // level-3 block sums
        for (int j = 0; j < B16; j++) {
            int k = lane * B16 + j;
            if (k >= N2) break;
            b3 = __fadd_rn(b3, B2[k]);
        }
        int hb = lane & 16;                            // level-4 prefixes
        float p4 = 0.0f;
        #pragma unroll
        for (int j = 0; j < B16; j++) {
            float t = __shfl_sync(0xffffffffu, b3, hb + j);
            if (j <= (lane & 15)) p4 = __fadd_rn(p4, t);
        }
        float b40 = __shfl_sync(0xffffffffu, p4, 15);  // naive scan(2)
        float r4  = (lane < 16) ? p4 : __fadd_rn(p4, b40);
        float off = __shfl_up_sync(0xffffffffu, r4, 1);
        float p = 0.0f;                                // corrected R3
        for (int j = 0; j < B16; j++) {
            int k = lane * B16 + j;
            if (k >= N2) break;
            p = __fadd_rn(p, B2[k]);
            sR3[k] = (lane > 0) ? __fadd_rn(p, off) : p;
        }
    }
    __syncthreads();

    if (tid < N2) {                                    // corrected R2 rows
        int r = tid;
        float off = (r > 0) ? sR3[r - 1] : 0.0f;
        int sbase = r * 17;
        float p = 0.0f;
        #pragma unroll
        for (int j = 0; j < B16; j++) {
            p = __fadd_rn(p, sb[sbase + j]);
            sb[sbase + j] = (r > 0) ? __fadd_rn(p, off) : p;  // fl(p+0)=p
        }
    }
    __syncthreads();

    float* R2 = g_R2 + seq * N1;
    for (int q = tid; q < N1; q += 512)
        R2[q] = sb[q + (q >> 4)];
}

// ---------------------------------------------------------------------------
// KT: transpose R2 [seq][m] -> R2T [b][m][h] so k_osc's offset loads coalesce.
// grid (250, 8) x 256, smem tile 60 x (32+1).
// ---------------------------------------------------------------------------
__global__ void __launch_bounds__(256) k_tr(void) {
    int b  = blockIdx.y;
    int m0 = blockIdx.x * 32;
    __shared__ float tile[NH * 33];
    for (int idx = threadIdx.x; idx < NH * 32; idx += 256) {
        int h = idx >> 5, mm = idx & 31;
        tile[h * 33 + mm] = g_R2[(size_t)(b * NH + h) * N1 + m0 + mm];
    }
    __syncthreads();
    for (int idx = threadIdx.x; idx < 32 * NH; idx += 256) {
        int mm = idx / NH, h = idx - mm * NH;
        g_R2T[((size_t)b * N1 + m0 + mm) * NH + h] = tile[h * 33 + mm];
    }
}

// ---------------------------------------------------------------------------
// K3: fused final. grid (2000, 8) x 256 = 4 slots x 64 threads.
// Thread h: 16-step P1 chain (z/amp loads hoisted, <=2 frames per block),
// S = fl(P1 + off) (off = R2T, coalesced; 0.0 exact for m==0), exact mod,
// __sinf, amp interp -> smem. Reduce: 4x15 partials on all 64 threads, then
// 16 threads combine + h-invariant loudness. Fully-masked (h,m) blocks skip.
// ---------------------------------------------------------------------------
__global__ void __launch_bounds__(256) k_osc(const float* __restrict__ loud,
                                             float* __restrict__ out) {
    int slot = threadIdx.x >> 6;
    int h    = threadIdx.x & 63;
    int m    = blockIdx.x * 4 + slot;                  // [0, 8000)
    int b    = blockIdx.y;
    float rpos = RPOS();

    __shared__ float shp[4 * NH * 17];
    __shared__ float aux[4 * 64];

    if (h < NH) {
        int l0 = m * B16;
        float posf = __fmul_rn((float)l0, rpos);
        int i0f = (int)posf; if (i0f > TT - 2) i0f = TT - 2;
        float posl = __fmul_rn((float)(l0 + 15), rpos);
        int i0l = (int)posl; if (i0l > TT - 2) i0l = TT - 2;

        const float* amb = g_am + (size_t)b * TT * NH + h;
        float af0 = __ldg(amb + i0f * NH);
        float af1 = __ldg(amb + (i0f + 1) * NH);
        float al1 = __ldg(amb + (i0l + 1) * NH);

        float* shrow = shp + (slot * NH + h) * 17;
        if ((af0 == 0.0f) & (af1 == 0.0f) & (al1 == 0.0f)) {
            #pragma unroll
            for (int j = 0; j < B16; j++) shrow[j] = 0.0f;   // exact +-0 terms
        } else {
            const float* zb = g_z + (size_t)b * TT * NH + h;
            float zf0 = __ldg(zb + i0f * NH), zf1 = __ldg(zb + (i0f + 1) * NH);
            float zl0 = __ldg(zb + i0l * NH), zl1 = __ldg(zb + (i0l + 1) * NH);
            float al0 = __ldg(amb + i0l * NH);
            float fi0f = (float)i0f, fi0l = (float)i0l;
            float off = (m > 0)
                ? __ldg(&g_R2T[((size_t)b * N1 + m - 1) * NH + h]) : 0.0f;

            float p = 0.0f, lf = (float)l0;
            #pragma unroll
            for (int j = 0; j < B16; j++) {
                float pos = __fmul_rn(lf, rpos);
                int i0 = (int)pos; if (i0 > TT - 2) i0 = TT - 2;
                bool sec = (i0 > i0f);
                float fi0 = sec ? fi0l : fi0f;
                float z0  = sec ? zl0  : zf0;
                float z1  = sec ? zl1  : zf1;
                float a0  = sec ? al0  : af0;
                float a1  = sec ? al1  : af1;
                float w   = __fsub_rn(pos, fi0);
                float omw = __fsub_rn(1.0f, w);
                p = __fadd_rn(p, __fadd_rn(__fmul_rn(z0, omw), __fmul_rn(z1, w)));
                float S  = __fadd_rn(p, off);              // off=0 exact for m==0
                float sn = __sinf(exact_mod_2pi(S));
                float av = __fadd_rn(__fmul_rn(a0, omw), __fmul_rn(a1, w));
                shrow[j] = __fmul_rn(av, sn);
                lf = __fadd_rn(lf, 1.0f);
            }
        }
    }
    __syncthreads();

    {   // 4 groups x 15 rows partial sums (sum order is output-level freedom)
        int g = h >> 4, c = h & 15;
        const float* base = shp + (slot * NH + g * 15) * 17 + c;
        float s = 0.0f;
        #pragma unroll
        for (int r = 0; r < 15; r++)
            s = __fadd_rn(s, base[r * 17]);
        aux[slot * 64 + h] = s;
    }
    __syncthreads();

    if (h < B16) {
        int t = m * B16 + h;
        float pos = __fmul_rn((float)t, rpos);
        int i0 = (int)pos; if (i0 > TT - 2) i0 = TT - 2;
        float w  = __fsub_rn(pos, (float)i0);
        const float* ldb = loud + b * TT;
        float lv = interp1(__ldg(ldb + i0), __ldg(ldb + i0 + 1), w);
        const float* a = aux + slot * 64 + h;
        float acc = __fadd_rn(__fadd_rn(a[0], a[16]), __fadd_rn(a[32], a[48]));
        out[(size_t)b * LL + t] = __fmul_rn(lv, acc);
    }
}

// ---------------------------------------------------------------------------
extern "C" void kernel_launch(void* const* d_in, const int* in_sizes, int n_in,
                              void* d_out, int out_size) {
    const float* f0   = (const float*)d_in[0];   // [8,500,1]
    const float* loud = (const float*)d_in[1];   // [8,500,1]
    const float* amps = (const float*)d_in[2];   // [8,500,60]
    float* out = (float*)d_out;                  // [8,128000]
    (void)in_sizes; (void)n_in; (void)out_size;

    k_z<<<(BB * TT * NH + 255) / 256, 256>>>(f0, amps);
    k_b1<<<15000, 256>>>();
    k_r2<<<SEQN, 512>>>();
    dim3 gt(N1 / 32, BB);
    k_tr<<<gt, 256>>>();
    dim3 g3(N1 / 4, BB);
    k_osc<<<g3, 256>>>(loud, out);
}

// round 15
// speedup vs baseline: 2.7231x; 1.1329x over previous
#include <cuda_runtime.h>

// ---------------------------------------------------------------------------
// OscillatorBank — XLA ReduceWindowRewriter(base_length=16) bit-replication.
// (Scheme confirmed R11; perf rounds since.) Phase path bit-identical.
//   f0:[8,500,1] loudness:[8,500,1] harm_amps:[8,500,60] -> signal:[8,128000]
// ---------------------------------------------------------------------------

#define BB    8
#define TT    500
#define NH    60
#define LL    128000
#define SEQN  (BB * NH)     // 480 (b,h) sequences
#define B16   16
#define N1    8000          // LL/16
#define N2    500           // N1/16

__device__ float g_z  [BB * TT * NH];  // fl(fl(f0*k)*CSC), layout [b][frame][h]
__device__ float g_am [BB * TT * NH];  // masked amps,      layout [b][frame][h]
__device__ float g_B1 [SEQN * N1];     // level-1 block sums
__device__ float g_B2 [SEQN * N2];     // level-2 block sums
__device__ float g_R2 [SEQN * N1];     // corrected level-2 values [seq][m]
__device__ float g_R2T[BB * N1 * NH];  // transposed: [b][m][h]

__device__ __forceinline__ float RPOS() { return __fdiv_rn(499.0f, 127999.0f); }
__device__ __forceinline__ float CSC()  { return (float)(6.283185307179586 / 16000.0); }
__device__ __forceinline__ float TPIF() { return (float)6.283185307179586; }

__device__ __forceinline__ float interp1(float a, float b, float w) {
    return __fadd_rn(__fmul_rn(a, __fsub_rn(1.0f, w)), __fmul_rn(b, w));
}

// Exact fmodf(x, fl32(2*pi)) for x >= 0 (bit-identical to jnp.mod for x>=0).
__device__ __forceinline__ float exact_mod_2pi(float x) {
    const float y = TPIF();
    float q = truncf(__fmul_rn(x, 0.15915494f));
    float r = __fmaf_rn(-q, y, x);
    if (r < 0.0f)     r = __fmaf_rn(-(q - 1.0f), y, x);
    else if (r >= y)  r = __fmaf_rn(-(q + 1.0f), y, x);
    return r;
}

// ---------------------------------------------------------------------------
// KZ: precompute z and masked-amp tables (bit-identical values). 240k threads.
// ---------------------------------------------------------------------------
__global__ void k_z(const float* __restrict__ f0, const float* __restrict__ amps) {
    int idx = blockIdx.x * blockDim.x + threadIdx.x;   // (b*500+i)*60+h
    if (idx >= BB * TT * NH) return;
    int h  = idx % NH;
    int bi = idx / NH;
    float f  = __ldg(f0 + bi);
    float kf = (float)(h + 1);
    float fk = __fmul_rn(f, kf);
    g_z[idx]  = __fmul_rn(fk, CSC());
    g_am[idx] = (fk > 8000.0f) ? 0.0f : __ldg(amps + idx);
}

// ---------------------------------------------------------------------------
// K1: level-1 block sums (16 leaves, strict left-to-right) + fused level-2
// sums via half-warp shuffles. A 16-block spans <=2 frames: z loads hoisted.
// grid 15000 x 256.
// ---------------------------------------------------------------------------
__global__ void __launch_bounds__(256) k_b1(void) {
    int gw   = blockIdx.x * 8 + (threadIdx.x >> 5);
    int lane = threadIdx.x & 31;
    int seq  = gw / 250;
    int pr   = gw - seq * 250;
    int row  = pr * 2 + (lane >> 4);                   // [0,500)
    int m    = row * B16 + (lane & 15);                // [0,8000)
    int b = seq / NH, h = seq - b * NH;
    float rpos = RPOS();
    const float* zb = g_z + (size_t)b * TT * NH + h;

    int l0 = m * B16;
    float posf = __fmul_rn((float)l0, rpos);
    int i0f = (int)posf; if (i0f > TT - 2) i0f = TT - 2;
    float posl = __fmul_rn((float)(l0 + 15), rpos);
    int i0l = (int)posl; if (i0l > TT - 2) i0l = TT - 2;
    float zf0 = __ldg(zb + i0f * NH), zf1 = __ldg(zb + (i0f + 1) * NH);
    float zl0 = __ldg(zb + i0l * NH), zl1 = __ldg(zb + (i0l + 1) * NH);
    float fi0f = (float)i0f, fi0l = (float)i0l;

    float p = 0.0f, lf = (float)l0;
    #pragma unroll
    for (int j = 0; j < B16; j++) {
        float pos = __fmul_rn(lf, rpos);
        int i0 = (int)pos; if (i0 > TT - 2) i0 = TT - 2;
        bool sec = (i0 > i0f);
        float fi0 = sec ? fi0l : fi0f;
        float z0  = sec ? zl0  : zf0;
        float z1  = sec ? zl1  : zf1;
        float w   = __fsub_rn(pos, fi0);
        float omw = __fsub_rn(1.0f, w);
        p  = __fadd_rn(p, __fadd_rn(__fmul_rn(z0, omw), __fmul_rn(z1, w)));
        lf = __fadd_rn(lf, 1.0f);                      // exact (< 2^24)
    }
    g_B1[seq * N1 + m] = p;

    // B2[row] = sequential left-to-right sum of the 16 lane values
    int base = (lane & 16);
    float s = 0.0f;
    #pragma unroll
    for (int j = 0; j < B16; j++)
        s = __fadd_rn(s, __shfl_sync(0xffffffffu, p, base + j));
    if ((lane & 15) == 0)
        g_B2[seq * N2 + row] = s;
}

// ---------------------------------------------------------------------------
// K2: fused levels 3..5 (warp 0 -> smem R3) + corrected level-2 R2[8000].
// CTA per seq, smem-staged with stride-17 padding. grid 480 x 512.
// ---------------------------------------------------------------------------
__global__ void __launch_bounds__(512) k_r2(void) {
    int seq = blockIdx.x;
    int tid = threadIdx.x;
    __shared__ float sb[8500];                         // 8000 + row pads
    __shared__ float sR3[N2];

    const float* B1 = g_B1 + seq * N1;
    for (int q = tid; q < N1; q += 512)
        sb[q + (q >> 4)] = B1[q];

    if (tid < 32) {                                    // warp 0: R3[500]
        int lane = tid;
        const float* B2 = g_B2 + seq * N2;
        float b3 = 0.0f;                               // level-3 block sums
        for (int j = 0; j < B16; j++) {
            int k = lane * B16 + j;
            if (k >= N2) break;
            b3 = __fadd_rn(b3, B2[k]);
        }
        int hb = lane & 16;                            // level-4 prefixes
        float p4 = 0.0f;
        #pragma unroll
        for (int j = 0; j < B16; j++) {
            float t = __shfl_sync(0xffffffffu, b3, hb + j);
            if (j <= (lane & 15)) p4 = __fadd_rn(p4, t);
        }
        float b40 = __shfl_sync(0xffffffffu, p4, 15);  // naive scan(2)
        float r4  = (lane < 16) ? p4 : __fadd_rn(p4, b40);
        float off = __shfl_up_sync(0xffffffffu, r4, 1);
        float p = 0.0f;                                // corrected R3
        for (int j = 0; j < B16; j++) {
            int k = lane * B16 + j;
            if (k >= N2) break;
            p = __fadd_rn(p, B2[k]);
            sR3[k] = (lane > 0) ? __fadd_rn(p, off) : p;
        }
    }
    __syncthreads();

    if (tid < N2) {                                    // corrected R2 rows
        int r = tid;
        float off = (r > 0) ? sR3[r - 1] : 0.0f;
        int sbase = r * 17;
        float p = 0.0f;
        #pragma unroll
        for (int j = 0; j < B16; j++) {
            p = __fadd_rn(p, sb[sbase + j]);
            sb[sbase + j] = (r > 0) ? __fadd_rn(p, off) : p;  // fl(p+0)=p
        }
    }
    __syncthreads();

    float* R2 = g_R2 + seq * N1;
    for (int q = tid; q < N1; q += 512)
        R2[q] = sb[q + (q >> 4)];
}

// ---------------------------------------------------------------------------
// KT: transpose R2 [seq][m] -> R2T [b][m][h]. 80x60 tiles, float4 loads,
// pad-85 smem (conflict-free), coalesced flat stores. grid (100, 8) x 256.
// ---------------------------------------------------------------------------
__global__ void __launch_bounds__(256) k_tr(void) {
    int b  = blockIdx.y;
    int m0 = blockIdx.x * 80;
    __shared__ float tile[NH * 85];                    // [h][mm], pad 85

    // load: 60 rows x 20 float4 (80 consecutive m per row)
    for (int idx = threadIdx.x; idx < NH * 20; idx += 256) {
        int h = idx / 20, q4 = idx - h * 20;
        const float4* src = reinterpret_cast<const float4*>(
            &g_R2[(size_t)(b * NH + h) * N1 + m0 + q4 * 4]);
        float4 v = __ldg(src);
        int base = h * 85 + q4 * 4;
        tile[base]     = v.x;
        tile[base + 1] = v.y;
        tile[base + 2] = v.z;
        tile[base + 3] = v.w;
    }
    __syncthreads();

    // store: flat = mm*60+h, contiguous in R2T
    float* dst = g_R2T + ((size_t)b * N1 + m0) * NH;
    for (int idx = threadIdx.x; idx < 80 * NH; idx += 256) {
        int mm = idx / NH, h = idx - mm * NH;
        dst[idx] = tile[h * 85 + mm];
    }
}

// ---------------------------------------------------------------------------
// K3: fused final. grid (2000, 8) x 256 = 4 slots x 64 threads.
// Per slot, 16 threads precompute float4(w, 1-w, sec) for the 16 j's (shared
// by all 60 h-threads). Straddle (<=1 frame boundary, slot-uniform) splits a
// no-select fast path from a select path where zl0==zf1, al0==af1.
// S = fl(P1 + off) (off coalesced from R2T; 0.0 exact for m==0), exact mod,
// __sinf, amp interp -> smem; 4x15 partials + 16-thread combine + loudness.
// ---------------------------------------------------------------------------
__global__ void __launch_bounds__(256) k_osc(const float* __restrict__ loud,
                                             float* __restrict__ out) {
    int slot = threadIdx.x >> 6;
    int h    = threadIdx.x & 63;
    int m    = blockIdx.x * 4 + slot;                  // [0, 8000)
    int b    = blockIdx.y;
    float rpos = RPOS();
    int l0 = m * B16;

    __shared__ float4 sws[4][B16];
    __shared__ float  shp[4 * NH * 17];
    __shared__ float  aux[4 * 64];

    if (h < B16) {                                     // per-j shared tables
        int t = l0 + h;
        float pos = __fmul_rn((float)t, rpos);
        int i0 = (int)pos; if (i0 > TT - 2) i0 = TT - 2;
        float posf = __fmul_rn((float)l0, rpos);
        int i0f = (int)posf; if (i0f > TT - 2) i0f = TT - 2;
        float w = __fsub_rn(pos, (float)i0);
        sws[slot][h] = make_float4(w, __fsub_rn(1.0f, w),
                                   (i0 > i0f) ? 1.0f : 0.0f, 0.0f);
    }
    __syncthreads();

    if (h < NH) {
        float posf = __fmul_rn((float)l0, rpos);
        int i0f = (int)posf; if (i0f > TT - 2) i0f = TT - 2;
        float posl = __fmul_rn((float)(l0 + 15), rpos);
        int i0l = (int)posl; if (i0l > TT - 2) i0l = TT - 2;

        const float* amb = g_am + (size_t)b * TT * NH + h;
        float af0 = __ldg(amb + i0f * NH);
        float af1 = __ldg(amb + (i0f + 1) * NH);
        float al1 = __ldg(amb + (i0l + 1) * NH);

        float* shrow = shp + (slot * NH + h) * 17;
        if ((af0 == 0.0f) & (af1 == 0.0f) & (al1 == 0.0f)) {
            #pragma unroll
            for (int j = 0; j < B16; j++) shrow[j] = 0.0f;   // exact +-0 terms
        } else {
            const float* zb = g_z + (size_t)b * TT * NH + h;
            float zf0 = __ldg(zb + i0f * NH), zf1 = __ldg(zb + (i0f + 1) * NH);
            float off = (m > 0)
                ? __ldg(&g_R2T[((size_t)b * N1 + m - 1) * NH + h]) : 0.0f;
            float p = 0.0f;

            if (i0l == i0f) {                          // slot-uniform fast path
                #pragma unroll
                for (int j = 0; j < B16; j++) {
                    float4 ws = sws[slot][j];
                    p = __fadd_rn(p, __fadd_rn(__fmul_rn(zf0, ws.y),
                                               __fmul_rn(zf1, ws.x)));
                    float S  = __fadd_rn(p, off);      // off=0 exact for m==0
                    float sn = __sinf(exact_mod_2pi(S));
                    float av = __fadd_rn(__fmul_rn(af0, ws.y),
                                         __fmul_rn(af1, ws.x));
                    shrow[j] = __fmul_rn(av, sn);
                }
            } else {                                   // straddle: i0l = i0f+1
                float zl1 = __ldg(zb + (i0l + 1) * NH);
                #pragma unroll
                for (int j = 0; j < B16; j++) {
                    float4 ws = sws[slot][j];
                    bool sec = (ws.z != 0.0f);
                    float z0 = sec ? zf1 : zf0;        // zl0 == zf1
                    float z1 = sec ? zl1 : zf1;
                    float a0 = sec ? af1 : af0;        // al0 == af1
                    float a1 = sec ? al1 : af1;
                    p = __fadd_rn(p, __fadd_rn(__fmul_rn(z0, ws.y),
                                               __fmul_rn(z1, ws.x)));
                    float S  = __fadd_rn(p, off);
                    float sn = __sinf(exact_mod_2pi(S));
                    float av = __fadd_rn(__fmul_rn(a0, ws.y),
                                         __fmul_rn(a1, ws.x));
                    shrow[j] = __fmul_rn(av, sn);
                }
            }
        }
    }
    __syncthreads();

    {   // 4 groups x 15 rows partial sums (sum order is output-level freedom)
        int g = h >> 4, c = h & 15;
        const float* base = shp + (slot * NH + g * 15) * 17 + c;
        float s = 0.0f;
        #pragma unroll
        for (int r = 0; r < 15; r++)
            s = __fadd_rn(s, base[r * 17]);
        aux[slot * 64 + h] = s;
    }
    __syncthreads();

    if (h < B16) {
        int t = l0 + h;
        float pos = __fmul_rn((float)t, rpos);
        int i0 = (int)pos; if (i0 > TT - 2) i0 = TT - 2;
        float w  = __fsub_rn(pos, (float)i0);
        const float* ldb = loud + b * TT;
        float lv = interp1(__ldg(ldb + i0), __ldg(ldb + i0 + 1), w);
        const float* a = aux + slot * 64 + h;
        float acc = __fadd_rn(__fadd_rn(a[0], a[16]), __fadd_rn(a[32], a[48]));
        out[(size_t)b * LL + t] = __fmul_rn(lv, acc);
    }
}

// ---------------------------------------------------------------------------
extern "C" void kernel_launch(void* const* d_in, const int* in_sizes, int n_in,
                              void* d_out, int out_size) {
    const float* f0   = (const float*)d_in[0];   // [8,500,1]
    const float* loud = (const float*)d_in[1];   // [8,500,1]
    const float* amps = (const float*)d_in[2];   // [8,500,60]
    float* out = (float*)d_out;                  // [8,128000]
    (void)in_sizes; (void)n_in; (void)out_size;

    k_z<<<(BB * TT * NH + 255) / 256, 256>>>(f0, amps);
    k_b1<<<15000, 256>>>();
    k_r2<<<SEQN, 512>>>();
    dim3 gt(N1 / 80, BB);
    k_tr<<<gt, 256>>>();
    dim3 g3(N1 / 4, BB);
    k_osc<<<g3, 256>>>(loud, out);
}